// round 5
// baseline (speedup 1.0000x reference)
#include <cuda_runtime.h>

#define NB 65536
#define NL 1024
#define FULLM 0xFFFFFFFFu

// ---------------- device scratch (module-initialized; k_out restores state) ----------------
__device__ float         g_e[NB];                 // per-row raw energy S1/S2
__device__ unsigned char g_am[NB];                // per-row is_defect flag
__device__ double g_acc[3] = {0.0, 0.0, 0.0};     // [0]=wave, [1]=cls nll, [2]=penalty
__device__ int    g_cnt = 0;                      // n_valid labels
__device__ int    g_maxo = (int)0x80000000;       // global max, ordered-int encoding

__device__ __forceinline__ int   f2o(float f){ int i=__float_as_int(f); return i>=0 ? i : (i^0x7FFFFFFF); }
__device__ __forceinline__ float o2f(int i){ return __int_as_float(i>=0 ? i : (i^0x7FFFFFFF)); }

// ---------------- K1: warp-per-row streaming pass + CE epilogue ----------------
// block = 256 threads = 8 warps = 8 rows; grid = 8192.
// Thread `lane` loads float4 indices {32*i + lane}, i=0..7 (coalesced, MLP=8).
__global__ void __launch_bounds__(256, 6) k_row(const float4* __restrict__ wave,
                                                const float*  __restrict__ depth,
                                                const float4* __restrict__ logits,
                                                const long long* __restrict__ labels){
    const int lane = threadIdx.x & 31;
    const int wid  = threadIdx.x >> 5;
    const int row  = blockIdx.x * 8 + wid;
    const float4* rp = wave + (size_t)row * 256u;

    float4 r[8];
    #pragma unroll
    for (int i = 0; i < 8; i++) r[i] = rp[32*i + lane];

    const float tpos = __ldg(&depth[row]) * 10.0f;   // (2*d/4000)*20000

    float ws = 0.0f, S1 = 0.0f, S2 = 0.0f;
    float mx = -3.402823466e+38f;

    #pragma unroll
    for (int i = 0; i < 8; i++) {
        float4 v = r[i];
        mx = fmaxf(mx, fmaxf(fmaxf(v.x, v.y), fmaxf(v.z, v.w)));

        // Gaussian window (sigma = 5): only threads near tpos pay for exp
        float j = (float)(128*i + 4*lane);
        if (fabsf(j + 1.5f - tpos) < 51.5f) {
            float d0 = j        - tpos;  float e0 = __expf(-0.02f*d0*d0);
            float d1 = j + 1.0f - tpos;  float e1 = __expf(-0.02f*d1*d1);
            float d2 = j + 2.0f - tpos;  float e2 = __expf(-0.02f*d2*d2);
            float d3 = j + 3.0f - tpos;  float e3 = __expf(-0.02f*d3*d3);
            S2 += (e0 + e1) + (e2 + e3);
            S1 += fmaf(v.x*v.x, e0, fmaf(v.y*v.y, e1, fmaf(v.z*v.z, e2, v.w*v.w*e3)));
        }

        // neighbors via single rotate-shuffle each (boundary value folded in)
        float prevw = (i > 0) ? r[i-1].w : 0.0f;
        float nextx = (i < 7) ? r[i+1].x : 0.0f;
        float lm = __shfl_sync(FULLM, (lane == 31) ? prevw : v.w, (lane + 31) & 31);
        float rn = __shfl_sync(FULLM, (lane == 0)  ? nextx : v.x, (lane + 1)  & 31);

        float d0 = (i == 0 && lane == 0)  ? (v.y - v.x)
                                          : (fmaf(-2.0f, v.x, v.y) + lm);
        float d1 = fmaf(-2.0f, v.y, v.z) + v.x;
        float d2 = fmaf(-2.0f, v.z, v.w) + v.y;
        float d3 = (i == 7 && lane == 31) ? (v.z - v.w)
                                          : (fmaf(-2.0f, v.w, rn) + v.z);
        ws += fmaf(d0, d0, fmaf(d1, d1, fmaf(d2, d2, d3*d3)));
    }
    ws *= 9900.0f * 9900.0f;   // (1/DT^2 - C^2/DX^2)^2

    #pragma unroll
    for (int o = 16; o > 0; o >>= 1) {
        ws += __shfl_xor_sync(FULLM, ws, o);
        S1 += __shfl_xor_sync(FULLM, S1, o);
        S2 += __shfl_xor_sync(FULLM, S2, o);
    }
    int mo = __reduce_max_sync(FULLM, f2o(mx));

    // per-warp epilogue by lane 0: energy store + CE + argmax flag
    __shared__ float sw[8], scc[8];
    __shared__ int   smx[8], scn[8];
    if (lane == 0) {
        g_e[row] = S1 / S2;

        float4 lg = logits[row];
        long long lab = labels[row];
        int am = 0; float bm = lg.x;                  // first-occurrence argmax
        if (lg.y > bm) { bm = lg.y; am = 1; }
        if (lg.z > bm) { bm = lg.z; am = 2; }
        if (lg.w > bm) { bm = lg.w; am = 3; }
        g_am[row] = (unsigned char)(am >= 2);

        float ce = 0.0f; int valid = 0;
        if (lab != -1ll) {
            float se = __expf(lg.x - bm) + __expf(lg.y - bm)
                     + __expf(lg.z - bm) + __expf(lg.w - bm);
            int li = (int)lab;
            float sel = (li == 0) ? lg.x : (li == 1) ? lg.y : (li == 2) ? lg.z : lg.w;
            ce = bm + __logf(se) - sel;
            valid = 1;
        }
        sw[wid] = ws;  smx[wid] = mo;  scc[wid] = ce;  scn[wid] = valid;
    }
    __syncthreads();
    if (threadIdx.x == 0) {
        float W = sw[0], C = scc[0]; int M = smx[0], N = scn[0];
        #pragma unroll
        for (int i = 1; i < 8; i++) {
            W += sw[i];  C += scc[i];  N += scn[i];
            M = (smx[i] > M) ? smx[i] : M;
        }
        atomicAdd(&g_acc[0], (double)W);
        atomicAdd(&g_acc[1], (double)C);
        atomicAdd(&g_cnt, N);
        atomicMax(&g_maxo, M);
    }
}

// ---------------- K2: penalty only (4 rows/thread, tiny traffic) ----------------
__global__ void __launch_bounds__(256) k_fin(){
    const int t = blockIdx.x * 256 + threadIdx.x;        // 16384 threads
    const float gmax = o2f(g_maxo);
    const float inv  = 1.0f / (20.0f * gmax);

    float4 e4 = ((const float4*)g_e)[t];                 // rows 4t..4t+3
    uchar4 a4 = ((const uchar4*)g_am)[t];
    const float ev[4] = {e4.x, e4.y, e4.z, e4.w};
    const unsigned char av[4] = {a4.x, a4.y, a4.z, a4.w};

    float pS = 0.0f;
    #pragma unroll
    for (int k = 0; k < 4; k++) {
        float e = ev[k] * inv;
        if (av[k]) { float d = 0.1f - e; pS += (e < 0.1f) ? d*d : 0.0f; }
        else       { float d = e - 0.5f; pS += (e > 0.5f) ? d*d : 0.0f; }
    }

    #pragma unroll
    for (int o = 16; o > 0; o >>= 1)
        pS += __shfl_xor_sync(FULLM, pS, o);
    __shared__ float sps[8];
    int lane = threadIdx.x & 31, wid = threadIdx.x >> 5;
    if (lane == 0) sps[wid] = pS;
    __syncthreads();
    if (threadIdx.x == 0) {
        #pragma unroll
        for (int i = 1; i < 8; i++) pS += sps[i];
        atomicAdd(&g_acc[2], (double)pS);
    }
}

// ---------------- K3: finalize + restore accumulator state for next replay ----------------
__global__ void k_out(float* __restrict__ out){
    double wave = g_acc[0] * (1.0 / ((double)NB * (double)NL));
    double cls  = (g_cnt > 0) ? (g_acc[1] / (double)g_cnt) : 0.0;
    double phys = g_acc[2] * (1.0 / (double)NB);
    out[0] = (float)(cls + 0.1 * wave + 0.1 * phys);
    out[1] = (float)cls;
    out[2] = (float)wave;
    out[3] = (float)phys;
    // reset-after-use: leave globals in their initial state
    g_acc[0] = 0.0; g_acc[1] = 0.0; g_acc[2] = 0.0;
    g_cnt = 0; g_maxo = (int)0x80000000;
}

// ---------------- launch ----------------
extern "C" void kernel_launch(void* const* d_in, const int* in_sizes, int n_in,
                              void* d_out, int out_size){
    const float4*    wave   = (const float4*)d_in[0];
    const float4*    logits = (const float4*)d_in[1];
    const float*     depth  = (const float*)d_in[2];
    const long long* labels = (const long long*)d_in[3];

    k_row<<<NB/8, 256>>>(wave, depth, logits, labels);
    k_fin<<<NB/1024, 256>>>();
    k_out<<<1, 1>>>((float*)d_out);
}

// round 8
// speedup vs baseline: 1.1719x; 1.1719x over previous
#include <cuda_runtime.h>

#define NB 65536
#define NL 1024
#define FULLM 0xFFFFFFFFu

// ---------------- device scratch (module-initialized; last block restores state) ----------------
__device__ float  g_e[NB];                        // per-row raw energy S1/S2
__device__ double g_acc[3] = {0.0, 0.0, 0.0};     // [0]=wave, [1]=cls nll, [2]=penalty
__device__ int    g_cnt = 0;                      // n_valid labels
__device__ int    g_maxo = (int)0x80000000;       // global max, ordered-int encoding
__device__ int    g_ticket = 0;                   // last-block-done ticket for k_fin

__device__ __forceinline__ int   f2o(float f){ int i=__float_as_int(f); return i>=0 ? i : (i^0x7FFFFFFF); }
__device__ __forceinline__ float o2f(int i){ return __int_as_float(i>=0 ? i : (i^0x7FFFFFFF)); }

// ---------------- K1: warp-per-row streaming pass (R4 shape: regs free, MLP=8) ----------------
// block = 256 threads = 8 warps = 8 rows; grid = 8192.
// Thread `lane` loads float4 indices {32*i + lane}, i=0..7 (coalesced, front-batched).
__global__ void __launch_bounds__(256) k_row(const float4* __restrict__ wave,
                                             const float*  __restrict__ depth){
    const int lane = threadIdx.x & 31;
    const int wid  = threadIdx.x >> 5;
    const int row  = blockIdx.x * 8 + wid;
    const float4* rp = wave + (size_t)row * 256u;

    float4 r[8];
    #pragma unroll
    for (int i = 0; i < 8; i++) r[i] = __ldcs(&rp[32*i + lane]);   // read-once: evict-first

    const float tpos = __ldg(&depth[row]) * 10.0f;   // (2*d/4000)*20000

    float ws = 0.0f, S1 = 0.0f, S2 = 0.0f;
    float mx = -3.402823466e+38f;

    #pragma unroll
    for (int i = 0; i < 8; i++) {
        float4 v = r[i];
        mx = fmaxf(mx, fmaxf(fmaxf(v.x, v.y), fmaxf(v.z, v.w)));

        // Gaussian window (sigma = 5): only threads near tpos pay for exp
        float j = (float)(128*i + 4*lane);
        if (fabsf(j + 1.5f - tpos) < 51.5f) {
            float d0 = j        - tpos;  float e0 = __expf(-0.02f*d0*d0);
            float d1 = j + 1.0f - tpos;  float e1 = __expf(-0.02f*d1*d1);
            float d2 = j + 2.0f - tpos;  float e2 = __expf(-0.02f*d2*d2);
            float d3 = j + 3.0f - tpos;  float e3 = __expf(-0.02f*d3*d3);
            S2 += (e0 + e1) + (e2 + e3);
            S1 += fmaf(v.x*v.x, e0, fmaf(v.y*v.y, e1, fmaf(v.z*v.z, e2, v.w*v.w*e3)));
        }

        // neighbors for the second difference (R4 shape)
        float lm = __shfl_up_sync  (FULLM, v.w, 1);
        float rn = __shfl_down_sync(FULLM, v.x, 1);
        float lmB = (i > 0) ? __shfl_sync(FULLM, r[i-1].w, 31) : 0.0f;
        float rnB = (i < 7) ? __shfl_sync(FULLM, r[i+1].x, 0)  : 0.0f;
        if (lane == 0)  lm = lmB;
        if (lane == 31) rn = rnB;

        float d0 = (i == 0 && lane == 0)  ? (v.y - v.x)
                                          : (fmaf(-2.0f, v.x, v.y) + lm);
        float d1 = fmaf(-2.0f, v.y, v.z) + v.x;
        float d2 = fmaf(-2.0f, v.z, v.w) + v.y;
        float d3 = (i == 7 && lane == 31) ? (v.z - v.w)
                                          : (fmaf(-2.0f, v.w, rn) + v.z);
        ws += fmaf(d0, d0, fmaf(d1, d1, fmaf(d2, d2, d3*d3)));
    }
    ws *= 9900.0f * 9900.0f;   // (1/DT^2 - C^2/DX^2)^2

    #pragma unroll
    for (int o = 16; o > 0; o >>= 1) {
        ws += __shfl_xor_sync(FULLM, ws, o);
        S1 += __shfl_xor_sync(FULLM, S1, o);
        S2 += __shfl_xor_sync(FULLM, S2, o);
        mx  = fmaxf(mx, __shfl_xor_sync(FULLM, mx, o));
    }

    __shared__ float sw[8], sm[8];
    if (lane == 0) {
        g_e[row] = S1 / S2;
        sw[wid] = ws;  sm[wid] = mx;
    }
    __syncthreads();
    if (threadIdx.x == 0) {
        float W = sw[0], M = sm[0];
        #pragma unroll
        for (int i = 1; i < 8; i++) { W += sw[i]; M = fmaxf(M, sm[i]); }
        atomicAdd(&g_acc[0], (double)W);
        atomicMax(&g_maxo, f2o(M));
    }
}

// ---------------- K2: CE + argmax + penalty + finalize (last-block-done) ----------------
__global__ void __launch_bounds__(256) k_fin(const float4* __restrict__ logits,
                                             const longlong2* __restrict__ lab2,
                                             float* __restrict__ out){
    const int t = blockIdx.x * 256 + threadIdx.x;        // 16384 threads, 4 rows each
    const float gmax = o2f(g_maxo);
    const float inv  = 1.0f / (20.0f * gmax);

    float4 e4 = ((const float4*)g_e)[t];                 // rows 4t..4t+3
    const float ev[4] = {e4.x, e4.y, e4.z, e4.w};
    longlong2 la = lab2[2*t], lb = lab2[2*t+1];
    const long long lv[4] = {la.x, la.y, lb.x, lb.y};

    float cS = 0.0f, pS = 0.0f; int cnt = 0;
    #pragma unroll
    for (int k = 0; k < 4; k++) {
        float4 lg = logits[4*t + k];

        int am = 0; float bm = lg.x;                     // first-occurrence argmax
        if (lg.y > bm) { bm = lg.y; am = 1; }
        if (lg.z > bm) { bm = lg.z; am = 2; }
        if (lg.w > bm) { bm = lg.w; am = 3; }

        float e = ev[k] * inv;
        if (am >= 2) { float d = 0.1f - e; pS += (e < 0.1f) ? d*d : 0.0f; }
        else         { float d = e - 0.5f; pS += (e > 0.5f) ? d*d : 0.0f; }

        long long lab = lv[k];
        if (lab != -1ll) {
            float se = __expf(lg.x - bm) + __expf(lg.y - bm)
                     + __expf(lg.z - bm) + __expf(lg.w - bm);
            float lse = bm + __logf(se);
            int li = (int)lab;
            float sel = (li == 0) ? lg.x : (li == 1) ? lg.y : (li == 2) ? lg.z : lg.w;
            cS += lse - sel;
            cnt++;
        }
    }

    #pragma unroll
    for (int o = 16; o > 0; o >>= 1) {
        cS  += __shfl_xor_sync(FULLM, cS, o);
        pS  += __shfl_xor_sync(FULLM, pS, o);
        cnt += __shfl_xor_sync(FULLM, cnt, o);
    }
    __shared__ float scs[8], sps[8]; __shared__ int sn[8];
    int lane = threadIdx.x & 31, wid = threadIdx.x >> 5;
    if (lane == 0) { scs[wid]=cS; sps[wid]=pS; sn[wid]=cnt; }
    __syncthreads();
    if (threadIdx.x == 0) {
        #pragma unroll
        for (int i = 1; i < 8; i++) { cS+=scs[i]; pS+=sps[i]; cnt+=sn[i]; }
        atomicAdd(&g_acc[1], (double)cS);
        atomicAdd(&g_acc[2], (double)pS);
        atomicAdd(&g_cnt, cnt);

        __threadfence();
        int tk = atomicAdd(&g_ticket, 1);
        if (tk == gridDim.x - 1) {                       // last block: finalize + reset
            double wave = g_acc[0] * (1.0 / ((double)NB * (double)NL));
            double cls  = (g_cnt > 0) ? (g_acc[1] / (double)g_cnt) : 0.0;
            double phys = g_acc[2] * (1.0 / (double)NB);
            out[0] = (float)(cls + 0.1 * wave + 0.1 * phys);
            out[1] = (float)cls;
            out[2] = (float)wave;
            out[3] = (float)phys;
            // reset-after-use: leave globals in initial state for next replay
            g_acc[0] = 0.0; g_acc[1] = 0.0; g_acc[2] = 0.0;
            g_cnt = 0; g_maxo = (int)0x80000000; g_ticket = 0;
        }
    }
}

// ---------------- launch ----------------
extern "C" void kernel_launch(void* const* d_in, const int* in_sizes, int n_in,
                              void* d_out, int out_size){
    const float4*    wave   = (const float4*)d_in[0];
    const float4*    logits = (const float4*)d_in[1];
    const float*     depth  = (const float*)d_in[2];
    const longlong2* lab    = (const longlong2*)d_in[3];

    k_row<<<NB/8, 256>>>(wave, depth);
    k_fin<<<NB/1024, 256>>>(logits, lab, (float*)d_out);
}